// round 2
// baseline (speedup 1.0000x reference)
#include <cuda_runtime.h>
#include <math.h>

#define Bc 2
#define Mc 8192
#define Nc (Bc * Mc)
#define KF 16
#define KN 8
#define NB 4096          // rank buckets per cloud
#define BCAP 64          // max members per bucket (Poisson(2) tail ~1e-60)

// Scratch (device globals: no allocation allowed)
__device__ int    g_knn[(size_t)Nc * KF];
__device__ double g_acc[8];
__device__ int    g_hist[Bc][NB];
__device__ int    g_pref[Bc][NB];
__device__ int    g_members[Bc][NB * BCAP];

// ======================= kNN: warp-per-query =======================
// Block = 512 threads (16 warps), grid = 148 (74 blocks per cloud).
// Whole cloud (8192 x float4, w = |c|^2) staged in 128KB dynamic smem.
// Each warp owns one query at a time; the warp's top-32 candidates live
// one-per-lane; threshold = warp max (shfl butterfly). d2' = |c|^2 - 2 q.c
// is monotone in true distance (per-query constant |q|^2 dropped).

#define KNN_THREADS 512
#define KNN_WARPS 16
#define BLK_PER_CLOUD 74

__device__ __forceinline__ void warp_maxarg(float v, int lane, float& m, int& ml) {
    float bm = v; int bl = lane;
#pragma unroll
    for (int o = 16; o; o >>= 1) {
        float om = __shfl_xor_sync(0xffffffffu, bm, o);
        int   ol = __shfl_xor_sync(0xffffffffu, bl, o);
        if (om > bm || (om == bm && ol > bl)) { bm = om; bl = ol; }
    }
    m = bm; ml = bl;
}

extern "C" __global__ void __launch_bounds__(KNN_THREADS, 1)
knn_kernel(const float* __restrict__ coords) {
    extern __shared__ float4 sh[];

    const int tid = threadIdx.x;
    const int cloud = blockIdx.x / BLK_PER_CLOUD;
    const int blockInCloud = blockIdx.x % BLK_PER_CLOUD;

    const float* cb = coords + (size_t)cloud * Mc * 3;
    for (int i = tid; i < Mc; i += KNN_THREADS) {
        float x = cb[3 * i], y = cb[3 * i + 1], z = cb[3 * i + 2];
        sh[i] = make_float4(x, y, z, fmaf(x, x, fmaf(y, y, z * z)));
    }
    __syncthreads();

    const int lane = tid & 31;
    const int warpId = tid >> 5;
    const int WARPS_PER_CLOUD = BLK_PER_CLOUD * KNN_WARPS;   // 1184
    const int goff = cloud * Mc;

    for (int q = blockInCloud * KNN_WARPS + warpId; q < Mc; q += WARPS_PER_CLOUD) {
        const float4 qc = sh[q];
        const float qx = -2.0f * qc.x;
        const float qy = -2.0f * qc.y;
        const float qz = -2.0f * qc.z;

        // seed: first 32 candidates, one per lane
        float myD; int myI;
        {
            float4 c = sh[lane];
            myD = fmaf(qx, c.x, fmaf(qy, c.y, fmaf(qz, c.z, c.w)));
            myI = lane;
        }
        float mx; int mxLane;
        warp_maxarg(myD, lane, mx, mxLane);

        const float4* p = sh + 32;
#pragma unroll 1
        for (int iter = 1; iter < Mc / 32; ++iter, p += 32) {
            float4 c = p[lane];
            float d = fmaf(qx, c.x, fmaf(qy, c.y, fmaf(qz, c.z, c.w)));
            unsigned mask = __ballot_sync(0xffffffffu, d < mx);
            if (mask) {
                const int jbase = iter * 32;
                do {
                    const int src = __ffs(mask) - 1;
                    mask &= mask - 1;
                    const float dn = __shfl_sync(0xffffffffu, d, src);
                    if (dn < mx) {   // re-check: mx tightens as we insert
                        if (lane == mxLane) { myD = dn; myI = jbase + src; }
                        warp_maxarg(myD, lane, mx, mxLane);
                    }
                } while (mask);
            }
        }

        // bitonic sort of 32 (d, idx) across lanes, ascending lexicographic
#pragma unroll
        for (int k = 2; k <= 32; k <<= 1) {
#pragma unroll
            for (int j = k >> 1; j; j >>= 1) {
                float od = __shfl_xor_sync(0xffffffffu, myD, j);
                int   oi = __shfl_xor_sync(0xffffffffu, myI, j);
                bool up = ((lane & k) == 0);
                bool lower = ((lane & j) == 0);
                bool oLtMine = (od < myD) || (od == myD && oi < myI);
                bool take = (lower == up) ? oLtMine : !oLtMine;
                if (take) { myD = od; myI = oi; }
            }
        }
        if (lane < KF)
            g_knn[((size_t)goff + q) * KF + lane] = goff + myI;
    }
}

// ======================= rank bucketing (replaces sort) =======================
__global__ void zero_kernel() {
    const int t = blockIdx.x * blockDim.x + threadIdx.x;
    if (t < 8) g_acc[t] = 0.0;
    for (int i = t; i < Bc * NB; i += gridDim.x * blockDim.x)
        ((int*)g_hist)[i] = 0;
}

__global__ void rank_build_kernel(const float* __restrict__ scores) {
    const int i = blockIdx.x * blockDim.x + threadIdx.x;
    if (i >= Nc) return;
    const int cloud = i >> 13;
    const int local = i & (Mc - 1);
    const float s = scores[i];
    int b = (int)(s * (float)NB);
    b = b < 0 ? 0 : (b > NB - 1 ? NB - 1 : b);
    const int slot = atomicAdd(&g_hist[cloud][b], 1);
    if (slot < BCAP) g_members[cloud][b * BCAP + slot] = local;
}

__global__ void prefix_kernel() {
    __shared__ int sc[1024];
    const int cloud = blockIdx.x;
    const int t = threadIdx.x;
    const int base = t * 4;
    int h0 = g_hist[cloud][base + 0];
    int h1 = g_hist[cloud][base + 1];
    int h2 = g_hist[cloud][base + 2];
    int h3 = g_hist[cloud][base + 3];
    int sum = h0 + h1 + h2 + h3;
    sc[t] = sum;
    __syncthreads();
    for (int off = 1; off < 1024; off <<= 1) {
        int v = (t >= off) ? sc[t - off] : 0;
        __syncthreads();
        sc[t] += v;
        __syncthreads();
    }
    int excl = sc[t] - sum;
    g_pref[cloud][base + 0] = excl; excl += h0;
    g_pref[cloud][base + 1] = excl; excl += h1;
    g_pref[cloud][base + 2] = excl; excl += h2;
    g_pref[cloud][base + 3] = excl;
}

// ======================= per-point losses (+ rank dist loss) =======================
__global__ void loss_points_kernel(const float* __restrict__ scores,
                                   const float* __restrict__ coords) {
    const int i = blockIdx.x * blockDim.x + threadIdx.x;
    double acc[6] = {0, 0, 0, 0, 0, 0};  // num, wsum, pos, neg, smooth, dist

    {
        const float si = scores[i];
        const float xi = coords[3 * i], yi = coords[3 * i + 1], zi = coords[3 * i + 2];
        float nsum = 0.0f;
        const int* nb = g_knn + (size_t)i * KF;
#pragma unroll
        for (int r = 0; r < KF; ++r) {
            const int n = nb[r];
            const float sn = scores[n];
            const float sd = fabsf(si - sn);
            const float x = (1.0f - sd) * 2.0f;
            const float sig = 1.0f / (1.0f + expf(-x));
            if (r < KN) {
                const float dx = xi - coords[3 * n];
                const float dy = yi - coords[3 * n + 1];
                const float dz = zi - coords[3 * n + 2];
                const float dist = sqrtf(dx * dx + dy * dy + dz * dz);
                const float w = expf(-dist * 10.0f);
                acc[0] += (double)(w * sd * sd);
                acc[1] += (double)w;
                acc[2] += (double)logf(sig + 1e-8f);
                nsum += sn;
            } else {
                acc[3] += (double)logf(1.0f - sig + 1e-8f);
            }
        }
        const float dm = si - nsum * 0.125f;
        acc[4] = (double)(dm * dm);

        // ---- rank-based dist loss ----
        const int cloud = i >> 13;
        const int local = i & (Mc - 1);
        int b = (int)(si * (float)NB);
        b = b < 0 ? 0 : (b > NB - 1 ? NB - 1 : b);
        int cnt = g_hist[cloud][b];
        cnt = cnt > BCAP ? BCAP : cnt;
        int r = 0;
        const int* mem = &g_members[cloud][b * BCAP];
        for (int k = 0; k < cnt; ++k) {
            const int m = mem[k];
            const float sm = scores[(cloud << 13) + m];
            r += (sm < si) || (sm == si && m < local);
        }
        const int rank = g_pref[cloud][b] + r;
        const float df = si - (float)rank * (1.0f / (float)(Mc - 1));
        acc[5] = (double)(df * df);
    }

    // warp reduce -> smem per-warp -> block reduce -> 6 atomics per block
    const int lane = threadIdx.x & 31;
    const int wid = threadIdx.x >> 5;
#pragma unroll
    for (int k = 0; k < 6; ++k)
#pragma unroll
        for (int o = 16; o; o >>= 1)
            acc[k] += __shfl_down_sync(0xffffffffu, acc[k], o);

    __shared__ double red[8][6];
    if (lane == 0)
#pragma unroll
        for (int k = 0; k < 6; ++k) red[wid][k] = acc[k];
    __syncthreads();
    if (wid == 0 && lane < 6) {
        double s = 0.0;
#pragma unroll
        for (int w = 0; w < 8; ++w) s += red[w][lane];
        atomicAdd(&g_acc[lane], s);
    }
}

// ======================= finalize =======================
__global__ void finalize_kernel(float* out) {
    const double l_loc = g_acc[0] / fmax(g_acc[1], 1e-8);
    const double l_pos = -g_acc[2] / (double)((size_t)Nc * KN);
    const double l_neg = -g_acc[3] / (double)((size_t)Nc * KN);
    const double l_con = l_pos + l_neg;
    const double l_smooth = g_acc[4] / (double)Nc;
    const double l_dist = g_acc[5] / (double)Nc;
    out[0] = (float)(1.0 * l_loc + 0.5 * l_con + 0.3 * l_dist + 0.2 * l_smooth);
}

extern "C" void kernel_launch(void* const* d_in, const int* in_sizes, int n_in,
                              void* d_out, int out_size) {
    const float* scores = (const float*)d_in[0];
    const float* coords = (const float*)d_in[1];
    (void)in_sizes; (void)n_in; (void)out_size;

    cudaFuncSetAttribute(knn_kernel,
                         cudaFuncAttributeMaxDynamicSharedMemorySize,
                         Mc * (int)sizeof(float4));

    zero_kernel<<<16, 1024>>>();
    rank_build_kernel<<<Nc / 256, 256>>>(scores);
    prefix_kernel<<<Bc, 1024>>>();
    knn_kernel<<<Bc * BLK_PER_CLOUD, KNN_THREADS, Mc * sizeof(float4)>>>(coords);
    loss_points_kernel<<<Nc / 256, 256>>>(scores, coords);
    finalize_kernel<<<1, 1>>>((float*)d_out);
}